// round 8
// baseline (speedup 1.0000x reference)
#include <cuda_runtime.h>
#include <cuda_bf16.h>

#define N_IMG 128
#define KVI   16
typedef unsigned long long ull;

__device__ float g_partial[N_IMG * 20];
__device__ float g_qout[N_IMG * 10];
__device__ unsigned int g_tick;

__device__ __forceinline__ ull pk2(float lo, float hi) {
    ull r; asm("mov.b64 %0,{%1,%2};" : "=l"(r) : "f"(lo), "f"(hi)); return r;
}
__device__ __forceinline__ void upk2(ull v, float& lo, float& hi) {
    asm("mov.b64 {%0,%1},%2;" : "=f"(lo), "=f"(hi) : "l"(v));
}
__device__ __forceinline__ void fma2(ull& d, ull a, ull b) {
    asm("fma.rn.f32x2 %0,%1,%2,%3;" : "=l"(d) : "l"(a), "l"(b), "l"(d));
}

// ---- shared memory layout (float offsets) ----------------------------------
#define SM_WQF2 0        // 8640: fine q weights as (w,w) pairs, (k,c,cin,ky,kx)
#define SM_WQC4 8640     // 3840: coarse q weights float4 {w0,w1,w2,pad}
#define SM_WCF  12480    // 162
#define SM_WCC  12642    // 162
#define SM_W5F  12804    // 50
#define SM_W5C  12854    // 50
#define SM_RED  12904    // 320
#define SM_SC   13224    // 1024 coarse sums 32x32
#define SM_ME   14248    // 4488: m E-pairs  33rp x 68 x 2
#define SM_MO   18736    // 4352: m O-pairs  32rp x 68 x 2
#define SM_RE   23088    // 4488: r E-pairs
#define SM_RO   27576    // 4352: r O-pairs
// phase region (A: X/X1/R1/CVA/CVB, B: v pair buffers)
#define SM_X    31928    // 9248: X pad-2 (also raw wh/wr staging first)
#define SM_X1   41176    // 2592
#define SM_R1   43768    // 1156
#define SM_CVA  44924    // 1156
#define SM_CVB  46080    // 1156
#define SM_VAE  31928    // 4488
#define SM_VAO  36416    // 4352
#define SM_VBE  40768    // 4488
#define SM_VBO  45256    // 4352 -> ends 49608
#define SM_TOT  49608
#define SMEM_BYTES (SM_TOT * 4)
#define NEGINF __int_as_float(0xff800000)

// write value at padded (p,x) into both parity arrays of a fine field
__device__ __forceinline__ void wpair(float* sm, int eb, int ob, int p, int x, float v) {
    sm[eb + (p >> 1) * 136 + 2 * x + (p & 1)] = v;
    sm[ob + ((p - 1) >> 1) * 136 + 2 * x + (1 - (p & 1))] = v;
}

// fused r = conv_r(conv_h(.)) front-end (interior 5x5 / border WC, bit-exact)
template <int H, int ROW, int CHS>
__device__ __forceinline__ float rfront(const float* sxb, const float* w5,
                                        const float* wc, int y, int x) {
    float acc = 0.f;
    if (y >= 1 && y <= H - 2 && x >= 1 && x <= H - 2) {
#pragma unroll
        for (int ci = 0; ci < 2; ci++) {
            const float* xb = &sxb[ci * CHS + y * ROW + x];
#pragma unroll
            for (int fy = 0; fy < 5; fy++)
#pragma unroll
                for (int fx = 0; fx < 5; fx++)
                    acc = fmaf(w5[ci * 25 + fy * 5 + fx], xb[fy * ROW + fx], acc);
        }
    } else {
#pragma unroll
        for (int jy = 0; jy < 3; jy++)
#pragma unroll
            for (int jx = 0; jx < 3; jx++) {
                int py = y + jy - 1, px = x + jx - 1;
                if (py >= 0 && py < H && px >= 0 && px < H) {
                    const float* wcj = &wc[(jy * 3 + jx) * 18];
#pragma unroll
                    for (int ci = 0; ci < 2; ci++) {
                        const float* xb = &sxb[ci * CHS + (py + 1) * ROW + (px + 1)];
#pragma unroll
                        for (int iy = 0; iy < 3; iy++)
#pragma unroll
                            for (int ix = 0; ix < 3; ix++)
                                acc = fmaf(wcj[ci * 9 + iy * 3 + ix], xb[iy * ROW + ix], acc);
                    }
                }
            }
    }
    return acc;
}

__global__ __launch_bounds__(512) void k_main(
    const float* __restrict__ X, const int* __restrict__ S1, const int* __restrict__ S2,
    const float* __restrict__ wqf, const float* __restrict__ wqc,
    const float* __restrict__ whf, const float* __restrict__ wrf,
    const float* __restrict__ whc, const float* __restrict__ wrc,
    const float* __restrict__ gamma, const float* __restrict__ beta,
    const float* __restrict__ dw1, const float* __restrict__ dw2,
    float* __restrict__ out) {
    extern __shared__ float sm[];
    ull* smu = (ull*)sm;
    const int t = threadIdx.x, n = blockIdx.x;

    // ---- stage weights ---------------------------------------------------
    for (int i = t; i < 4320; i += 512) {
        float w = wqf[i];
        sm[SM_WQF2 + 2 * i] = w; sm[SM_WQF2 + 2 * i + 1] = w;
    }
    for (int i = t; i < 960; i += 512) {
        int kc = i / 6, rm = i % 6;
        const float* s = wqc + kc * 18 + (rm / 3) * 9 + (rm % 3) * 3;
        float4 v; v.x = s[0]; v.y = s[1]; v.z = s[2]; v.w = 0.f;
        ((float4*)&sm[SM_WQC4])[i] = v;
    }
    for (int i = t; i < 2700; i += 512) sm[SM_X + i] = whf[i];
    for (int i = t; i < 1350; i += 512) sm[SM_X + 2700 + i] = wrf[i];
    for (int i = t; i < 2700; i += 512) sm[SM_X + 4050 + i] = whc[i];
    for (int i = t; i < 1350; i += 512) sm[SM_X + 6750 + i] = wrc[i];
    __syncthreads();

    // ---- compose WC ------------------------------------------------------
    if (t < 324) {
        int lvl = t / 162, rem = t % 162;
        int j = rem / 18, ci = (rem % 18) / 9, i = rem % 9;
        const float* wr = &sm[SM_X + (lvl ? 6750 : 2700)];
        const float* wh = &sm[SM_X + (lvl ? 4050 : 0)];
        float acc = 0.f;
        for (int o = 0; o < 150; o++)
            acc = fmaf(wr[o * 9 + j], wh[(o * 2 + ci) * 9 + i], acc);
        sm[(lvl ? SM_WCC : SM_WCF) + rem] = acc;
    }
    __syncthreads();

    // ---- W5 + zero pair regions ------------------------------------------
    if (t < 100) {
        int lvl = t / 50, rem = t % 50;
        int ci = rem / 25, f = rem % 25, fy = f / 5, fx = f % 5;
        const float* wc = &sm[lvl ? SM_WCC : SM_WCF];
        float acc = 0.f;
        for (int jy = 0; jy < 3; jy++)
            for (int jx = 0; jx < 3; jx++) {
                int iy = fy - jy, ix = fx - jx;
                if (iy >= 0 && iy <= 2 && ix >= 0 && ix <= 2)
                    acc += wc[(jy * 3 + jx) * 18 + ci * 9 + iy * 3 + ix];
            }
        sm[(lvl ? SM_W5C : SM_W5F) + rem] = acc;
    }
    for (int i = SM_ME + t; i < SM_TOT; i += 512) sm[i] = 0.f;
    __syncthreads();

    // ---- X into pad-2 smem ----------------------------------------------
    for (int i = t; i < 8192; i += 512) {
        int ci = i >> 12, y = (i >> 6) & 63, x = i & 63;
        sm[SM_X + ci * 4624 + (y + 2) * 68 + (x + 2)] = X[n * 8192 + i];
    }
    __syncthreads();

    // ---- maxpool ----------------------------------------------------------
    for (int i = t; i < 2048; i += 512) {
        int ci = i >> 10, y = (i >> 5) & 31, x = i & 31;
        const float* b = &sm[SM_X + ci * 4624 + (2 * y + 2) * 68 + (2 * x + 2)];
        sm[SM_X1 + ci * 1296 + (y + 2) * 36 + (x + 2)] =
            fmaxf(fmaxf(b[0], b[1]), fmaxf(b[68], b[69]));
    }
    __syncthreads();

    // ---- coarse r1 --------------------------------------------------------
    for (int i = t; i < 1024; i += 512) {
        int y = i >> 5, x = i & 31;
        sm[SM_R1 + (y + 1) * 34 + (x + 1)] =
            rfront<32, 36, 1296>(&sm[SM_X1], &sm[SM_W5C], &sm[SM_WCC], y, x);
    }
    __syncthreads();

    // ---- coarse VI (scalar, 2 px/thread, register sums) -------------------
    {
        const int cy = t >> 4, cx0 = (t & 15) * 2;
        float scs0 = 0.f, scs1 = 0.f;
        int vc = SM_CVA, vn = SM_CVB;
#pragma unroll 1
        for (int k = 0; k < KVI; k++) {
            float pin[2][3][4];
#pragma unroll
            for (int rr = 0; rr < 3; rr++) {
                float2 a = *(float2*)&sm[SM_R1 + (cy + rr) * 34 + cx0];
                float2 b = *(float2*)&sm[SM_R1 + (cy + rr) * 34 + cx0 + 2];
                pin[0][rr][0] = a.x; pin[0][rr][1] = a.y; pin[0][rr][2] = b.x; pin[0][rr][3] = b.y;
                float2 c2 = *(float2*)&sm[vc + (cy + rr) * 34 + cx0];
                float2 d2 = *(float2*)&sm[vc + (cy + rr) * 34 + cx0 + 2];
                pin[1][rr][0] = c2.x; pin[1][rr][1] = c2.y; pin[1][rr][2] = d2.x; pin[1][rr][3] = d2.y;
            }
            float m0 = NEGINF, m1 = NEGINF;
            const float4* w4 = (const float4*)&sm[SM_WQC4];
#pragma unroll 2
            for (int c = 0; c < 10; c++) {
                float a0 = 0.f, a1 = 0.f;
#pragma unroll
                for (int cin = 0; cin < 2; cin++)
#pragma unroll
                    for (int ky = 0; ky < 3; ky++) {
                        float4 w = w4[(k * 10 + c) * 6 + cin * 3 + ky];
                        const float* q = pin[cin][ky];
                        a0 = fmaf(w.x, q[0], a0); a0 = fmaf(w.y, q[1], a0); a0 = fmaf(w.z, q[2], a0);
                        a1 = fmaf(w.x, q[1], a1); a1 = fmaf(w.y, q[2], a1); a1 = fmaf(w.z, q[3], a1);
                    }
                m0 = fmaxf(m0, a0); m1 = fmaxf(m1, a1);
            }
            sm[vn + (cy + 1) * 34 + cx0 + 1] = m0;
            sm[vn + (cy + 1) * 34 + cx0 + 2] = m1;
            scs0 += m0; scs1 += m1;
            __syncthreads();
            int tp = vc; vc = vn; vn = tp;
        }
        sm[SM_SC + cy * 32 + cx0] = scs0;
        sm[SM_SC + cy * 32 + cx0 + 1] = scs1;
    }
    __syncthreads();

    // ---- upsample (sum/4; jax half-pixel linear == clamp) -> m pairs ------
    for (int i = t; i < 4096; i += 512) {
        int oy = i >> 6, ox = i & 63, ty = oy >> 1, tx = ox >> 1;
        int ya, yb, xa, xb; float wya, wyb, wxa, wxb;
        if ((oy & 1) == 0) { ya = ty > 0 ? ty - 1 : 0; yb = ty; wya = 0.25f; wyb = 0.75f; }
        else { ya = ty; yb = ty < 31 ? ty + 1 : 31; wya = 0.75f; wyb = 0.25f; }
        if ((ox & 1) == 0) { xa = tx > 0 ? tx - 1 : 0; xb = tx; wxa = 0.25f; wxb = 0.75f; }
        else { xa = tx; xb = tx < 31 ? tx + 1 : 31; wxa = 0.75f; wxb = 0.25f; }
        float v = wya * (wxa * sm[SM_SC + ya * 32 + xa] + wxb * sm[SM_SC + ya * 32 + xb]) +
                  wyb * (wxa * sm[SM_SC + yb * 32 + xa] + wxb * sm[SM_SC + yb * 32 + xb]);
        wpair(sm, SM_ME, SM_MO, oy + 1, ox + 1, v * 0.25f);
    }
    // ---- fine r front -> r pairs -----------------------------------------
    for (int i = t; i < 4096; i += 512) {
        int y = i >> 6, x = i & 63;
        wpair(sm, SM_RE, SM_RO, y + 1, x + 1,
              rfront<64, 68, 4624>(&sm[SM_X], &sm[SM_W5F], &sm[SM_WCF], y, x));
    }
    __syncthreads();
    // ---- phase B: zero v pair buffers (kills X/X1/R1/CV*) -----------------
    for (int i = SM_X + t; i < SM_TOT; i += 512) sm[i] = 0.f;
    __syncthreads();

    // ==== fine VI: 1 col x 4 row-pairs per thread, conflict-free FFMA2 ====
    const int xc = t & 63, xp = xc + 1;     // column (padded)
    const int Y = (t >> 6) * 4;             // base row-pair, {0,4,...,28}
    int vE = SM_VAE, vO = SM_VAO, nE = SM_VBE, nO = SM_VBO;
    float S[8];
#pragma unroll
    for (int j = 0; j < 8; j++) S[j] = 0.f;
#pragma unroll 1
    for (int k = 0; k < KVI; k++) {
        float M[8];
#pragma unroll
        for (int j = 0; j < 8; j++) M[j] = NEGINF;
        const int fE[3] = {SM_ME / 2 + Y * 68 + xp - 1,
                           SM_RE / 2 + Y * 68 + xp - 1,
                           vE / 2 + Y * 68 + xp - 1};
        const int fO[3] = {SM_MO / 2 + Y * 68 + xp - 1,
                           SM_RO / 2 + Y * 68 + xp - 1,
                           vO / 2 + Y * 68 + xp - 1};
#pragma unroll 1
        for (int ch0 = 0; ch0 < 10; ch0 += 2) {
            ull A[2][4];
#pragma unroll
            for (int cc = 0; cc < 2; cc++)
#pragma unroll
                for (int j = 0; j < 4; j++) A[cc][j] = 0ull;
#pragma unroll
            for (int f = 0; f < 3; f++) {
                ull qE[5][3], qO[4][3];
#pragma unroll
                for (int i = 0; i < 5; i++)
#pragma unroll
                    for (int c = 0; c < 3; c++) qE[i][c] = smu[fE[f] + i * 68 + c];
#pragma unroll
                for (int i = 0; i < 4; i++)
#pragma unroll
                    for (int c = 0; c < 3; c++) qO[i][c] = smu[fO[f] + i * 68 + c];
#pragma unroll
                for (int cc = 0; cc < 2; cc++) {
                    const ull* w = smu + (k * 10 + ch0 + cc) * 27 + f * 9;
                    ull w00 = w[0], w01 = w[1], w02 = w[2];
                    ull w10 = w[3], w11 = w[4], w12 = w[5];
                    ull w20 = w[6], w21 = w[7], w22 = w[8];
#pragma unroll
                    for (int j = 0; j < 4; j++) {
                        fma2(A[cc][j], w00, qE[j][0]);
                        fma2(A[cc][j], w01, qE[j][1]);
                        fma2(A[cc][j], w02, qE[j][2]);
                        fma2(A[cc][j], w10, qO[j][0]);
                        fma2(A[cc][j], w11, qO[j][1]);
                        fma2(A[cc][j], w12, qO[j][2]);
                        fma2(A[cc][j], w20, qE[j + 1][0]);
                        fma2(A[cc][j], w21, qE[j + 1][1]);
                        fma2(A[cc][j], w22, qE[j + 1][2]);
                    }
                }
            }
#pragma unroll
            for (int cc = 0; cc < 2; cc++)
#pragma unroll
                for (int j = 0; j < 4; j++) {
                    float lo, hi;
                    upk2(A[cc][j], lo, hi);
                    M[2 * j] = fmaxf(M[2 * j], lo);
                    M[2 * j + 1] = fmaxf(M[2 * j + 1], hi);
                }
        }
#pragma unroll
        for (int j = 0; j < 4; j++) {
            float vlo = M[2 * j], vhi = M[2 * j + 1];
            smu[nO / 2 + (Y + j) * 68 + xp] = pk2(vlo, vhi);
            sm[nE + (Y + j) * 136 + 2 * xp + 1] = vlo;
            sm[nE + (Y + j + 1) * 136 + 2 * xp] = vhi;
            S[2 * j] += vlo; S[2 * j + 1] += vhi;
        }
        __syncthreads();
        int tp = vE; vE = nE; nE = tp; tp = vO; vO = nO; nO = tp;
    }

    // ---- vbar into current v buffer --------------------------------------
#pragma unroll
    for (int j = 0; j < 4; j++) {
        wpair(sm, vE, vO, 2 * (Y + j) + 1, xp, S[2 * j] * (1.f / 16.f));
        wpair(sm, vE, vO, 2 * (Y + j) + 2, xp, S[2 * j + 1] * (1.f / 16.f));
    }
    __syncthreads();

    // ---- final q conv + BN partials + gather (R5 mapping) ----------------
    const int Y5 = t >> 4, x05 = (t & 15) * 4;
    float pin[3][4][6];
#pragma unroll
    for (int rr = 0; rr < 4; rr++) {
        int p = 2 * Y5 + rr;
#pragma unroll
        for (int cc = 0; cc < 6; cc++) {
            int x = x05 + cc, off = (p >> 1) * 136 + 2 * x + (p & 1);
            pin[0][rr][cc] = sm[SM_ME + off];
            pin[1][rr][cc] = sm[SM_RE + off];
            pin[2][rr][cc] = sm[vE + off];
        }
    }
    const int s1 = S1[n], s2 = S2[n];
    float psum[10], psq[10];
#pragma unroll 2
    for (int c = 0; c < 10; c++) {
        const int wb = 2 * ((15 * 10 + c) * 27);
        float a[2][4];
#pragma unroll
        for (int j = 0; j < 8; j++) a[j >> 2][j & 3] = 0.f;
#pragma unroll
        for (int cin = 0; cin < 3; cin++)
#pragma unroll
            for (int ky = 0; ky < 3; ky++)
#pragma unroll
                for (int kx = 0; kx < 3; kx++) {
                    float wv = sm[wb + 2 * (cin * 9 + ky * 3 + kx)];
#pragma unroll
                    for (int dr = 0; dr < 2; dr++)
#pragma unroll
                        for (int dc = 0; dc < 4; dc++)
                            a[dr][dc] = fmaf(wv, pin[cin][dr + ky][dc + kx], a[dr][dc]);
                }
        float s = 0.f, q = 0.f;
#pragma unroll
        for (int dr = 0; dr < 2; dr++)
#pragma unroll
            for (int dc = 0; dc < 4; dc++) {
                s += a[dr][dc]; q += a[dr][dc] * a[dr][dc];
                if (2 * Y5 + dr == s1 && x05 + dc == s2) g_qout[n * 10 + c] = a[dr][dc];
            }
        psum[c] = s; psq[c] = q;
    }

    // ---- block-reduce BN partials ----------------------------------------
    int lane = t & 31, wid = t >> 5;
#pragma unroll
    for (int c = 0; c < 10; c++) {
        float s = psum[c], q = psq[c];
#pragma unroll
        for (int o = 16; o > 0; o >>= 1) {
            s += __shfl_down_sync(0xffffffffu, s, o);
            q += __shfl_down_sync(0xffffffffu, q, o);
        }
        if (lane == 0) { sm[SM_RED + wid * 20 + c] = s; sm[SM_RED + wid * 20 + 10 + c] = q; }
    }
    __syncthreads();
    if (t < 20) {
        float s = 0.f;
        for (int w = 0; w < 16; w++) s += sm[SM_RED + w * 20 + t];
        g_partial[n * 20 + t] = s;
    }

    // ---- epilogue by last block ------------------------------------------
    __shared__ int s_last;
    if (t == 0) {
        __threadfence();
        s_last = (atomicAdd(&g_tick, 1u) == N_IMG - 1);
    }
    __syncthreads();
    if (!s_last) return;
    if (t == 0) g_tick = 0;
    __threadfence();

    __shared__ float sMean[10], sScale[10], sBeta[10];
    if (t < 10) {
        double s = 0.0, sq = 0.0;
        for (int nn = 0; nn < N_IMG; nn++) {
            s += (double)g_partial[nn * 20 + t];
            sq += (double)g_partial[nn * 20 + 10 + t];
        }
        double cnt = (double)N_IMG * 4096.0, mu = s / cnt, var = sq / cnt - mu * mu;
        sMean[t] = (float)mu;
        sScale[t] = (float)((double)gamma[t] / sqrt(var + 1e-5));
        sBeta[t] = beta[t];
    }
    __syncthreads();
    if (t < N_IMG) {
        float qn[10];
#pragma unroll
        for (int c = 0; c < 10; c++)
            qn[c] = (g_qout[t * 10 + c] - sMean[c]) * sScale[c] + sBeta[c];
        float av = 0.f;
#pragma unroll
        for (int c = 0; c < 10; c++) av += qn[c] * dw1[c];
        av = fmaxf(av, 0.f);
        float b[8], bm = 0.f;
#pragma unroll
        for (int j = 0; j < 8; j++) {
            float bb = 0.f;
#pragma unroll
            for (int c = 0; c < 10; c++) bb += qn[c] * dw2[j * 10 + c];
            bb = fmaxf(bb, 0.f);
            b[j] = bb; bm += bb;
        }
        bm *= 0.125f;
#pragma unroll
        for (int j = 0; j < 8; j++) out[t * 8 + j] = av + b[j] - bm;
    }
}

extern "C" void kernel_launch(void* const* d_in, const int* in_sizes, int n_in,
                              void* d_out, int out_size) {
    const float* X   = (const float*)d_in[0];
    const int*   S1  = (const int*)d_in[1];
    const int*   S2  = (const int*)d_in[2];
    const float* whf = (const float*)d_in[3];
    const float* wrf = (const float*)d_in[4];
    const float* wqf = (const float*)d_in[5];
    const float* gam = (const float*)d_in[6];
    const float* bet = (const float*)d_in[7];
    const float* w1  = (const float*)d_in[8];
    const float* w2  = (const float*)d_in[9];
    const float* whc = (const float*)d_in[10];
    const float* wrc = (const float*)d_in[11];
    const float* wqc = (const float*)d_in[12];

    cudaFuncSetAttribute(k_main, cudaFuncAttributeMaxDynamicSharedMemorySize, SMEM_BYTES);
    k_main<<<N_IMG, 512, SMEM_BYTES>>>(X, S1, S2, wqf, wqc, whf, wrf, whc, wrc,
                                       gam, bet, w1, w2, (float*)d_out);
}

// round 9
// speedup vs baseline: 2.0219x; 2.0219x over previous
#include <cuda_runtime.h>
#include <cuda_bf16.h>

#define N_IMG 128
#define KVI   16
typedef unsigned long long ull;

__device__ float g_partial[N_IMG * 20];
__device__ float g_qout[N_IMG * 10];
__device__ unsigned int g_tick;

__device__ __forceinline__ ull pk2(float lo, float hi) {
    ull r; asm("mov.b64 %0,{%1,%2};" : "=l"(r) : "f"(lo), "f"(hi)); return r;
}
__device__ __forceinline__ void upk2(ull v, float& lo, float& hi) {
    asm("mov.b64 {%0,%1},%2;" : "=f"(lo), "=f"(hi) : "l"(v));
}
__device__ __forceinline__ void fma2(ull& d, ull a, ull b) {
    asm("fma.rn.f32x2 %0,%1,%2,%3;" : "=l"(d) : "l"(a), "l"(b), "l"(d));
}

// ---- shared memory layout (float offsets) ----------------------------------
#define SM_WQF2 0        // 8640: fine q weights as (w,w) pairs, (k,c,cin,ky,kx)
#define SM_WQC4 8640     // 3840: coarse q weights float4 {w0,w1,w2,pad}
#define SM_WCF  12480    // 162
#define SM_WCC  12642    // 162
#define SM_W5F  12804    // 50
#define SM_W5C  12854    // 50
#define SM_RED  12904    // 320
#define SM_SC   13224    // 1024 coarse sums 32x32
#define SM_ME   14248    // 4488: m E-pairs  33rp x 68 x 2
#define SM_MO   18736    // 4352: m O-pairs  32rp x 68 x 2
#define SM_RE   23088    // 4488: r E-pairs
#define SM_RO   27576    // 4352: r O-pairs
// phase region (A: X/X1/R1/CVA/CVB, B: v pair buffers)
#define SM_X    31928    // 9248: X pad-2 (also raw wh/wr staging first)
#define SM_X1   41176    // 2592
#define SM_R1   43768    // 1156
#define SM_CVA  44924    // 1156
#define SM_CVB  46080    // 1156
#define SM_VAE  31928    // 4488
#define SM_VAO  36416    // 4352
#define SM_VBE  40768    // 4488
#define SM_VBO  45256    // 4352 -> ends 49608
#define SM_TOT  49608
#define SMEM_BYTES (SM_TOT * 4)
#define NEGINF __int_as_float(0xff800000)

// write value at padded (p,x) into both parity arrays of a fine field
__device__ __forceinline__ void wpair(float* sm, int eb, int ob, int p, int x, float v) {
    sm[eb + (p >> 1) * 136 + 2 * x + (p & 1)] = v;
    sm[ob + ((p - 1) >> 1) * 136 + 2 * x + (1 - (p & 1))] = v;
}

// fused r = conv_r(conv_h(.)) front-end (interior 5x5 / border WC, bit-exact)
template <int H, int ROW, int CHS>
__device__ __forceinline__ float rfront(const float* sxb, const float* w5,
                                        const float* wc, int y, int x) {
    float acc = 0.f;
    if (y >= 1 && y <= H - 2 && x >= 1 && x <= H - 2) {
#pragma unroll
        for (int ci = 0; ci < 2; ci++) {
            const float* xb = &sxb[ci * CHS + y * ROW + x];
#pragma unroll
            for (int fy = 0; fy < 5; fy++)
#pragma unroll
                for (int fx = 0; fx < 5; fx++)
                    acc = fmaf(w5[ci * 25 + fy * 5 + fx], xb[fy * ROW + fx], acc);
        }
    } else {
#pragma unroll
        for (int jy = 0; jy < 3; jy++)
#pragma unroll
            for (int jx = 0; jx < 3; jx++) {
                int py = y + jy - 1, px = x + jx - 1;
                if (py >= 0 && py < H && px >= 0 && px < H) {
                    const float* wcj = &wc[(jy * 3 + jx) * 18];
#pragma unroll
                    for (int ci = 0; ci < 2; ci++) {
                        const float* xb = &sxb[ci * CHS + (py + 1) * ROW + (px + 1)];
#pragma unroll
                        for (int iy = 0; iy < 3; iy++)
#pragma unroll
                            for (int ix = 0; ix < 3; ix++)
                                acc = fmaf(wcj[ci * 9 + iy * 3 + ix], xb[iy * ROW + ix], acc);
                    }
                }
            }
    }
    return acc;
}

__global__ __launch_bounds__(512) void k_main(
    const float* __restrict__ X, const int* __restrict__ S1, const int* __restrict__ S2,
    const float* __restrict__ wqf, const float* __restrict__ wqc,
    const float* __restrict__ whf, const float* __restrict__ wrf,
    const float* __restrict__ whc, const float* __restrict__ wrc,
    const float* __restrict__ gamma, const float* __restrict__ beta,
    const float* __restrict__ dw1, const float* __restrict__ dw2,
    float* __restrict__ out) {
    extern __shared__ float sm[];
    ull* smu = (ull*)sm;
    const int t = threadIdx.x, n = blockIdx.x;

    // ---- stage weights ---------------------------------------------------
    for (int i = t; i < 4320; i += 512) {
        float w = wqf[i];
        sm[SM_WQF2 + 2 * i] = w; sm[SM_WQF2 + 2 * i + 1] = w;
    }
    for (int i = t; i < 960; i += 512) {
        int kc = i / 6, rm = i % 6;
        const float* s = wqc + kc * 18 + (rm / 3) * 9 + (rm % 3) * 3;
        float4 v; v.x = s[0]; v.y = s[1]; v.z = s[2]; v.w = 0.f;
        ((float4*)&sm[SM_WQC4])[i] = v;
    }
    for (int i = t; i < 2700; i += 512) sm[SM_X + i] = whf[i];
    for (int i = t; i < 1350; i += 512) sm[SM_X + 2700 + i] = wrf[i];
    for (int i = t; i < 2700; i += 512) sm[SM_X + 4050 + i] = whc[i];
    for (int i = t; i < 1350; i += 512) sm[SM_X + 6750 + i] = wrc[i];
    __syncthreads();

    // ---- compose WC ------------------------------------------------------
    if (t < 324) {
        int lvl = t / 162, rem = t % 162;
        int j = rem / 18, ci = (rem % 18) / 9, i = rem % 9;
        const float* wr = &sm[SM_X + (lvl ? 6750 : 2700)];
        const float* wh = &sm[SM_X + (lvl ? 4050 : 0)];
        float acc = 0.f;
        for (int o = 0; o < 150; o++)
            acc = fmaf(wr[o * 9 + j], wh[(o * 2 + ci) * 9 + i], acc);
        sm[(lvl ? SM_WCC : SM_WCF) + rem] = acc;
    }
    __syncthreads();

    // ---- W5 + zero pair regions ------------------------------------------
    if (t < 100) {
        int lvl = t / 50, rem = t % 50;
        int ci = rem / 25, f = rem % 25, fy = f / 5, fx = f % 5;
        const float* wc = &sm[lvl ? SM_WCC : SM_WCF];
        float acc = 0.f;
        for (int jy = 0; jy < 3; jy++)
            for (int jx = 0; jx < 3; jx++) {
                int iy = fy - jy, ix = fx - jx;
                if (iy >= 0 && iy <= 2 && ix >= 0 && ix <= 2)
                    acc += wc[(jy * 3 + jx) * 18 + ci * 9 + iy * 3 + ix];
            }
        sm[(lvl ? SM_W5C : SM_W5F) + rem] = acc;
    }
    for (int i = SM_ME + t; i < SM_TOT; i += 512) sm[i] = 0.f;
    __syncthreads();

    // ---- X into pad-2 smem ----------------------------------------------
    for (int i = t; i < 8192; i += 512) {
        int ci = i >> 12, y = (i >> 6) & 63, x = i & 63;
        sm[SM_X + ci * 4624 + (y + 2) * 68 + (x + 2)] = X[n * 8192 + i];
    }
    __syncthreads();

    // ---- maxpool ----------------------------------------------------------
    for (int i = t; i < 2048; i += 512) {
        int ci = i >> 10, y = (i >> 5) & 31, x = i & 31;
        const float* b = &sm[SM_X + ci * 4624 + (2 * y + 2) * 68 + (2 * x + 2)];
        sm[SM_X1 + ci * 1296 + (y + 2) * 36 + (x + 2)] =
            fmaxf(fmaxf(b[0], b[1]), fmaxf(b[68], b[69]));
    }
    __syncthreads();

    // ---- coarse r1 --------------------------------------------------------
    for (int i = t; i < 1024; i += 512) {
        int y = i >> 5, x = i & 31;
        sm[SM_R1 + (y + 1) * 34 + (x + 1)] =
            rfront<32, 36, 1296>(&sm[SM_X1], &sm[SM_W5C], &sm[SM_WCC], y, x);
    }
    __syncthreads();

    // ---- coarse VI (scalar, 2 px/thread, register sums) -------------------
    {
        const int cy = t >> 4, cx0 = (t & 15) * 2;
        float scs0 = 0.f, scs1 = 0.f;
        int vc = SM_CVA, vn = SM_CVB;
#pragma unroll 1
        for (int k = 0; k < KVI; k++) {
            float pin[2][3][4];
#pragma unroll
            for (int rr = 0; rr < 3; rr++) {
                float2 a = *(float2*)&sm[SM_R1 + (cy + rr) * 34 + cx0];
                float2 b = *(float2*)&sm[SM_R1 + (cy + rr) * 34 + cx0 + 2];
                pin[0][rr][0] = a.x; pin[0][rr][1] = a.y; pin[0][rr][2] = b.x; pin[0][rr][3] = b.y;
                float2 c2 = *(float2*)&sm[vc + (cy + rr) * 34 + cx0];
                float2 d2 = *(float2*)&sm[vc + (cy + rr) * 34 + cx0 + 2];
                pin[1][rr][0] = c2.x; pin[1][rr][1] = c2.y; pin[1][rr][2] = d2.x; pin[1][rr][3] = d2.y;
            }
            float m0 = NEGINF, m1 = NEGINF;
            const float4* w4 = (const float4*)&sm[SM_WQC4];
#pragma unroll 2
            for (int c = 0; c < 10; c++) {
                float a0 = 0.f, a1 = 0.f;
#pragma unroll
                for (int cin = 0; cin < 2; cin++)
#pragma unroll
                    for (int ky = 0; ky < 3; ky++) {
                        float4 w = w4[(k * 10 + c) * 6 + cin * 3 + ky];
                        const float* q = pin[cin][ky];
                        a0 = fmaf(w.x, q[0], a0); a0 = fmaf(w.y, q[1], a0); a0 = fmaf(w.z, q[2], a0);
                        a1 = fmaf(w.x, q[1], a1); a1 = fmaf(w.y, q[2], a1); a1 = fmaf(w.z, q[3], a1);
                    }
                m0 = fmaxf(m0, a0); m1 = fmaxf(m1, a1);
            }
            sm[vn + (cy + 1) * 34 + cx0 + 1] = m0;
            sm[vn + (cy + 1) * 34 + cx0 + 2] = m1;
            scs0 += m0; scs1 += m1;
            __syncthreads();
            int tp = vc; vc = vn; vn = tp;
        }
        sm[SM_SC + cy * 32 + cx0] = scs0;
        sm[SM_SC + cy * 32 + cx0 + 1] = scs1;
    }
    __syncthreads();

    // ---- upsample (sum/4; jax half-pixel linear == clamp) -> m pairs ------
    for (int i = t; i < 4096; i += 512) {
        int oy = i >> 6, ox = i & 63, ty = oy >> 1, tx = ox >> 1;
        int ya, yb, xa, xb; float wya, wyb, wxa, wxb;
        if ((oy & 1) == 0) { ya = ty > 0 ? ty - 1 : 0; yb = ty; wya = 0.25f; wyb = 0.75f; }
        else { ya = ty; yb = ty < 31 ? ty + 1 : 31; wya = 0.75f; wyb = 0.25f; }
        if ((ox & 1) == 0) { xa = tx > 0 ? tx - 1 : 0; xb = tx; wxa = 0.25f; wxb = 0.75f; }
        else { xa = tx; xb = tx < 31 ? tx + 1 : 31; wxa = 0.75f; wxb = 0.25f; }
        float v = wya * (wxa * sm[SM_SC + ya * 32 + xa] + wxb * sm[SM_SC + ya * 32 + xb]) +
                  wyb * (wxa * sm[SM_SC + yb * 32 + xa] + wxb * sm[SM_SC + yb * 32 + xb]);
        wpair(sm, SM_ME, SM_MO, oy + 1, ox + 1, v * 0.25f);
    }
    // ---- fine r front -> r pairs -----------------------------------------
    for (int i = t; i < 4096; i += 512) {
        int y = i >> 6, x = i & 63;
        wpair(sm, SM_RE, SM_RO, y + 1, x + 1,
              rfront<64, 68, 4624>(&sm[SM_X], &sm[SM_W5F], &sm[SM_WCF], y, x));
    }
    __syncthreads();
    // ---- phase B: zero v pair buffers (kills X/X1/R1/CV*) -----------------
    for (int i = SM_X + t; i < SM_TOT; i += 512) sm[i] = 0.f;
    __syncthreads();

    // ==== fine VI: 1 col x 4 row-pairs/thread, conflict-free, low-pressure ==
    const int xc = t & 63, xp = xc + 1;     // column (padded)
    const int Y = (t >> 6) * 4;             // base row-pair, {0,4,...,28}
    int vE = SM_VAE, vO = SM_VAO, nE = SM_VBE, nO = SM_VBO;
    float S[8];
#pragma unroll
    for (int j = 0; j < 8; j++) S[j] = 0.f;
#pragma unroll 1
    for (int k = 0; k < KVI; k++) {
        float M[8];
#pragma unroll
        for (int j = 0; j < 8; j++) M[j] = NEGINF;
        const int e0b = SM_ME / 2 + Y * 68 + xp - 1;
        const int e1b = SM_RE / 2 + Y * 68 + xp - 1;
        const int e2b = vE / 2 + Y * 68 + xp - 1;
        const int o0b = SM_MO / 2 + Y * 68 + xp - 1;
        const int o1b = SM_RO / 2 + Y * 68 + xp - 1;
        const int o2b = vO / 2 + Y * 68 + xp - 1;
#pragma unroll 1
        for (int ch0 = 0; ch0 < 10; ch0 += 2) {
            ull A[2][4];
#pragma unroll
            for (int cc = 0; cc < 2; cc++)
#pragma unroll
                for (int j = 0; j < 4; j++) A[cc][j] = 0ull;
#pragma unroll
            for (int f = 0; f < 3; f++) {
                const int eb = (f == 0) ? e0b : (f == 1) ? e1b : e2b;
                const int ob = (f == 0) ? o0b : (f == 1) ? o1b : o2b;
#pragma unroll
                for (int kx = 0; kx < 3; kx++) {
                    const ull* qe = smu + eb + kx;
                    const ull* qo = smu + ob + kx;
                    ull e0 = qe[0], e1 = qe[68], e2 = qe[136], e3 = qe[204], e4 = qe[272];
                    ull o0 = qo[0], o1 = qo[68], o2 = qo[136], o3 = qo[204];
#pragma unroll
                    for (int cc = 0; cc < 2; cc++) {
                        const ull* w = smu + (k * 10 + ch0 + cc) * 27 + f * 9 + kx;
                        ull w0 = w[0], w1 = w[3], w2 = w[6];
                        fma2(A[cc][0], w0, e0); fma2(A[cc][0], w1, o0); fma2(A[cc][0], w2, e1);
                        fma2(A[cc][1], w0, e1); fma2(A[cc][1], w1, o1); fma2(A[cc][1], w2, e2);
                        fma2(A[cc][2], w0, e2); fma2(A[cc][2], w1, o2); fma2(A[cc][2], w2, e3);
                        fma2(A[cc][3], w0, e3); fma2(A[cc][3], w1, o3); fma2(A[cc][3], w2, e4);
                    }
                    asm volatile("" ::: "memory");  // bound load hoisting
                }
            }
#pragma unroll
            for (int cc = 0; cc < 2; cc++)
#pragma unroll
                for (int j = 0; j < 4; j++) {
                    float lo, hi;
                    upk2(A[cc][j], lo, hi);
                    M[2 * j] = fmaxf(M[2 * j], lo);
                    M[2 * j + 1] = fmaxf(M[2 * j + 1], hi);
                }
        }
#pragma unroll
        for (int j = 0; j < 4; j++) {
            float vlo = M[2 * j], vhi = M[2 * j + 1];
            smu[nO / 2 + (Y + j) * 68 + xp] = pk2(vlo, vhi);
            sm[nE + (Y + j) * 136 + 2 * xp + 1] = vlo;
            sm[nE + (Y + j + 1) * 136 + 2 * xp] = vhi;
            S[2 * j] += vlo; S[2 * j + 1] += vhi;
        }
        __syncthreads();
        int tp = vE; vE = nE; nE = tp; tp = vO; vO = nO; nO = tp;
    }

    // ---- vbar into current v buffer --------------------------------------
#pragma unroll
    for (int j = 0; j < 4; j++) {
        wpair(sm, vE, vO, 2 * (Y + j) + 1, xp, S[2 * j] * (1.f / 16.f));
        wpair(sm, vE, vO, 2 * (Y + j) + 2, xp, S[2 * j + 1] * (1.f / 16.f));
    }
    __syncthreads();

    // ---- final q conv + BN partials + gather -----------------------------
    const int Y5 = t >> 4, x05 = (t & 15) * 4;
    float pin[3][4][6];
#pragma unroll
    for (int rr = 0; rr < 4; rr++) {
        int p = 2 * Y5 + rr;
#pragma unroll
        for (int cc = 0; cc < 6; cc++) {
            int x = x05 + cc, off = (p >> 1) * 136 + 2 * x + (p & 1);
            pin[0][rr][cc] = sm[SM_ME + off];
            pin[1][rr][cc] = sm[SM_RE + off];
            pin[2][rr][cc] = sm[vE + off];
        }
    }
    const int s1 = S1[n], s2 = S2[n];
    float psum[10], psq[10];
#pragma unroll 2
    for (int c = 0; c < 10; c++) {
        const int wb = 2 * ((15 * 10 + c) * 27);
        float a[2][4];
#pragma unroll
        for (int j = 0; j < 8; j++) a[j >> 2][j & 3] = 0.f;
#pragma unroll
        for (int cin = 0; cin < 3; cin++)
#pragma unroll
            for (int ky = 0; ky < 3; ky++)
#pragma unroll
                for (int kx = 0; kx < 3; kx++) {
                    float wv = sm[wb + 2 * (cin * 9 + ky * 3 + kx)];
#pragma unroll
                    for (int dr = 0; dr < 2; dr++)
#pragma unroll
                        for (int dc = 0; dc < 4; dc++)
                            a[dr][dc] = fmaf(wv, pin[cin][dr + ky][dc + kx], a[dr][dc]);
                }
        float s = 0.f, q = 0.f;
#pragma unroll
        for (int dr = 0; dr < 2; dr++)
#pragma unroll
            for (int dc = 0; dc < 4; dc++) {
                s += a[dr][dc]; q += a[dr][dc] * a[dr][dc];
                if (2 * Y5 + dr == s1 && x05 + dc == s2) g_qout[n * 10 + c] = a[dr][dc];
            }
        psum[c] = s; psq[c] = q;
    }

    // ---- block-reduce BN partials ----------------------------------------
    int lane = t & 31, wid = t >> 5;
#pragma unroll
    for (int c = 0; c < 10; c++) {
        float s = psum[c], q = psq[c];
#pragma unroll
        for (int o = 16; o > 0; o >>= 1) {
            s += __shfl_down_sync(0xffffffffu, s, o);
            q += __shfl_down_sync(0xffffffffu, q, o);
        }
        if (lane == 0) { sm[SM_RED + wid * 20 + c] = s; sm[SM_RED + wid * 20 + 10 + c] = q; }
    }
    __syncthreads();
    if (t < 20) {
        float s = 0.f;
        for (int w = 0; w < 16; w++) s += sm[SM_RED + w * 20 + t];
        g_partial[n * 20 + t] = s;
    }

    // ---- epilogue by last block ------------------------------------------
    __shared__ int s_last;
    if (t == 0) {
        __threadfence();
        s_last = (atomicAdd(&g_tick, 1u) == N_IMG - 1);
    }
    __syncthreads();
    if (!s_last) return;
    if (t == 0) g_tick = 0;
    __threadfence();

    __shared__ float sMean[10], sScale[10], sBeta[10];
    if (t < 10) {
        double s = 0.0, sq = 0.0;
        for (int nn = 0; nn < N_IMG; nn++) {
            s += (double)g_partial[nn * 20 + t];
            sq += (double)g_partial[nn * 20 + 10 + t];
        }
        double cnt = (double)N_IMG * 4096.0, mu = s / cnt, var = sq / cnt - mu * mu;
        sMean[t] = (float)mu;
        sScale[t] = (float)((double)gamma[t] / sqrt(var + 1e-5));
        sBeta[t] = beta[t];
    }
    __syncthreads();
    if (t < N_IMG) {
        float qn[10];
#pragma unroll
        for (int c = 0; c < 10; c++)
            qn[c] = (g_qout[t * 10 + c] - sMean[c]) * sScale[c] + sBeta[c];
        float av = 0.f;
#pragma unroll
        for (int c = 0; c < 10; c++) av += qn[c] * dw1[c];
        av = fmaxf(av, 0.f);
        float b[8], bm = 0.f;
#pragma unroll
        for (int j = 0; j < 8; j++) {
            float bb = 0.f;
#pragma unroll
            for (int c = 0; c < 10; c++) bb += qn[c] * dw2[j * 10 + c];
            bb = fmaxf(bb, 0.f);
            b[j] = bb; bm += bb;
        }
        bm *= 0.125f;
#pragma unroll
        for (int j = 0; j < 8; j++) out[t * 8 + j] = av + b[j] - bm;
    }
}

extern "C" void kernel_launch(void* const* d_in, const int* in_sizes, int n_in,
                              void* d_out, int out_size) {
    const float* X   = (const float*)d_in[0];
    const int*   S1  = (const int*)d_in[1];
    const int*   S2  = (const int*)d_in[2];
    const float* whf = (const float*)d_in[3];
    const float* wrf = (const float*)d_in[4];
    const float* wqf = (const float*)d_in[5];
    const float* gam = (const float*)d_in[6];
    const float* bet = (const float*)d_in[7];
    const float* w1  = (const float*)d_in[8];
    const float* w2  = (const float*)d_in[9];
    const float* whc = (const float*)d_in[10];
    const float* wrc = (const float*)d_in[11];
    const float* wqc = (const float*)d_in[12];

    cudaFuncSetAttribute(k_main, cudaFuncAttributeMaxDynamicSharedMemorySize, SMEM_BYTES);
    k_main<<<N_IMG, 512, SMEM_BYTES>>>(X, S1, S2, wqf, wqc, whf, wrf, whc, wrc,
                                       gam, bet, w1, w2, (float*)d_out);
}

// round 10
// speedup vs baseline: 2.5371x; 1.2548x over previous
#include <cuda_runtime.h>
#include <cuda_bf16.h>

#define N_IMG 128
#define KVI   16
typedef unsigned long long ull;

__device__ float g_partial[N_IMG * 20];
__device__ float g_qout[N_IMG * 10];
__device__ unsigned int g_tick;

__device__ __forceinline__ ull pk2(float lo, float hi) {
    ull r; asm("mov.b64 %0,{%1,%2};" : "=l"(r) : "f"(lo), "f"(hi)); return r;
}
__device__ __forceinline__ void upk2(ull v, float& lo, float& hi) {
    asm("mov.b64 {%0,%1},%2;" : "=f"(lo), "=f"(hi) : "l"(v));
}
__device__ __forceinline__ void fma2(ull& d, ull a, ull b) {
    asm("fma.rn.f32x2 %0,%1,%2,%3;" : "=l"(d) : "l"(a), "l"(b), "l"(d));
}

// ---- shared memory layout (float offsets) ----------------------------------
#define SM_WQF2 0        // 8640: fine q weights as (w,w) pairs, (k,c,cin,ky,kx)
#define SM_WQC4 8640     // 3840: coarse q weights float4 {w0,w1,w2,pad}
#define SM_WCF  12480    // 162
#define SM_WCC  12642    // 162
#define SM_W5F  12804    // 50
#define SM_W5C  12854    // 50
#define SM_RED  12904    // 320
#define SM_SC   13224    // 1024 coarse sums 32x32
#define SM_ME   14248    // 4488: m E-pairs  33rp x 68 x 2
#define SM_MO   18736    // 4352: m O-pairs  32rp x 68 x 2
#define SM_RE   23088    // 4488: r E-pairs
#define SM_RO   27576    // 4352: r O-pairs
// phase region (A: X/X1/R1/CVA/CVB, B: v pair buffers)
#define SM_X    31928    // 9248: X pad-2 (also raw wh/wr staging first)
#define SM_X1   41176    // 2592
#define SM_R1   43768    // 1156
#define SM_CVA  44924    // 1156
#define SM_CVB  46080    // 1156
#define SM_VAE  31928    // 4488
#define SM_VAO  36416    // 4352
#define SM_VBE  40768    // 4488
#define SM_VBO  45256    // 4352 -> ends 49608
#define SM_TOT  49608
#define SMEM_BYTES (SM_TOT * 4)
#define NEGINF __int_as_float(0xff800000)

// write value at padded (p,x) into both parity arrays of a fine field
__device__ __forceinline__ void wpair(float* sm, int eb, int ob, int p, int x, float v) {
    sm[eb + (p >> 1) * 136 + 2 * x + (p & 1)] = v;
    sm[ob + ((p - 1) >> 1) * 136 + 2 * x + (1 - (p & 1))] = v;
}

// fused r = conv_r(conv_h(.)) front-end (interior 5x5 / border WC, bit-exact)
template <int H, int ROW, int CHS>
__device__ __forceinline__ float rfront(const float* sxb, const float* w5,
                                        const float* wc, int y, int x) {
    float acc = 0.f;
    if (y >= 1 && y <= H - 2 && x >= 1 && x <= H - 2) {
#pragma unroll
        for (int ci = 0; ci < 2; ci++) {
            const float* xb = &sxb[ci * CHS + y * ROW + x];
#pragma unroll
            for (int fy = 0; fy < 5; fy++)
#pragma unroll
                for (int fx = 0; fx < 5; fx++)
                    acc = fmaf(w5[ci * 25 + fy * 5 + fx], xb[fy * ROW + fx], acc);
        }
    } else {
#pragma unroll
        for (int jy = 0; jy < 3; jy++)
#pragma unroll
            for (int jx = 0; jx < 3; jx++) {
                int py = y + jy - 1, px = x + jx - 1;
                if (py >= 0 && py < H && px >= 0 && px < H) {
                    const float* wcj = &wc[(jy * 3 + jx) * 18];
#pragma unroll
                    for (int ci = 0; ci < 2; ci++) {
                        const float* xb = &sxb[ci * CHS + (py + 1) * ROW + (px + 1)];
#pragma unroll
                        for (int iy = 0; iy < 3; iy++)
#pragma unroll
                            for (int ix = 0; ix < 3; ix++)
                                acc = fmaf(wcj[ci * 9 + iy * 3 + ix], xb[iy * ROW + ix], acc);
                    }
                }
            }
    }
    return acc;
}

__global__ __launch_bounds__(512) void k_main(
    const float* __restrict__ X, const int* __restrict__ S1, const int* __restrict__ S2,
    const float* __restrict__ wqf, const float* __restrict__ wqc,
    const float* __restrict__ whf, const float* __restrict__ wrf,
    const float* __restrict__ whc, const float* __restrict__ wrc,
    const float* __restrict__ gamma, const float* __restrict__ beta,
    const float* __restrict__ dw1, const float* __restrict__ dw2,
    float* __restrict__ out) {
    extern __shared__ float sm[];
    ull* smu = (ull*)sm;
    const int t = threadIdx.x, n = blockIdx.x;

    // ---- stage weights ---------------------------------------------------
    for (int i = t; i < 4320; i += 512) {
        float w = wqf[i];
        sm[SM_WQF2 + 2 * i] = w; sm[SM_WQF2 + 2 * i + 1] = w;
    }
    for (int i = t; i < 960; i += 512) {
        int kc = i / 6, rm = i % 6;
        const float* s = wqc + kc * 18 + (rm / 3) * 9 + (rm % 3) * 3;
        float4 v; v.x = s[0]; v.y = s[1]; v.z = s[2]; v.w = 0.f;
        ((float4*)&sm[SM_WQC4])[i] = v;
    }
    for (int i = t; i < 2700; i += 512) sm[SM_X + i] = whf[i];
    for (int i = t; i < 1350; i += 512) sm[SM_X + 2700 + i] = wrf[i];
    for (int i = t; i < 2700; i += 512) sm[SM_X + 4050 + i] = whc[i];
    for (int i = t; i < 1350; i += 512) sm[SM_X + 6750 + i] = wrc[i];
    __syncthreads();

    // ---- compose WC ------------------------------------------------------
    if (t < 324) {
        int lvl = t / 162, rem = t % 162;
        int j = rem / 18, ci = (rem % 18) / 9, i = rem % 9;
        const float* wr = &sm[SM_X + (lvl ? 6750 : 2700)];
        const float* wh = &sm[SM_X + (lvl ? 4050 : 0)];
        float acc = 0.f;
        for (int o = 0; o < 150; o++)
            acc = fmaf(wr[o * 9 + j], wh[(o * 2 + ci) * 9 + i], acc);
        sm[(lvl ? SM_WCC : SM_WCF) + rem] = acc;
    }
    __syncthreads();

    // ---- W5 + zero pair regions ------------------------------------------
    if (t < 100) {
        int lvl = t / 50, rem = t % 50;
        int ci = rem / 25, f = rem % 25, fy = f / 5, fx = f % 5;
        const float* wc = &sm[lvl ? SM_WCC : SM_WCF];
        float acc = 0.f;
        for (int jy = 0; jy < 3; jy++)
            for (int jx = 0; jx < 3; jx++) {
                int iy = fy - jy, ix = fx - jx;
                if (iy >= 0 && iy <= 2 && ix >= 0 && ix <= 2)
                    acc += wc[(jy * 3 + jx) * 18 + ci * 9 + iy * 3 + ix];
            }
        sm[(lvl ? SM_W5C : SM_W5F) + rem] = acc;
    }
    for (int i = SM_ME + t; i < SM_TOT; i += 512) sm[i] = 0.f;
    __syncthreads();

    // ---- X into pad-2 smem ----------------------------------------------
    for (int i = t; i < 8192; i += 512) {
        int ci = i >> 12, y = (i >> 6) & 63, x = i & 63;
        sm[SM_X + ci * 4624 + (y + 2) * 68 + (x + 2)] = X[n * 8192 + i];
    }
    __syncthreads();

    // ---- maxpool ----------------------------------------------------------
    for (int i = t; i < 2048; i += 512) {
        int ci = i >> 10, y = (i >> 5) & 31, x = i & 31;
        const float* b = &sm[SM_X + ci * 4624 + (2 * y + 2) * 68 + (2 * x + 2)];
        sm[SM_X1 + ci * 1296 + (y + 2) * 36 + (x + 2)] =
            fmaxf(fmaxf(b[0], b[1]), fmaxf(b[68], b[69]));
    }
    __syncthreads();

    // ---- coarse r1 --------------------------------------------------------
    for (int i = t; i < 1024; i += 512) {
        int y = i >> 5, x = i & 31;
        sm[SM_R1 + (y + 1) * 34 + (x + 1)] =
            rfront<32, 36, 1296>(&sm[SM_X1], &sm[SM_W5C], &sm[SM_WCC], y, x);
    }
    __syncthreads();

    // ---- coarse VI (scalar, 2 px/thread, register sums) -------------------
    {
        const int cy = t >> 4, cx0 = (t & 15) * 2;
        float scs0 = 0.f, scs1 = 0.f;
        int vc = SM_CVA, vn = SM_CVB;
#pragma unroll 1
        for (int k = 0; k < KVI; k++) {
            float pin[2][3][4];
#pragma unroll
            for (int rr = 0; rr < 3; rr++) {
                float2 a = *(float2*)&sm[SM_R1 + (cy + rr) * 34 + cx0];
                float2 b = *(float2*)&sm[SM_R1 + (cy + rr) * 34 + cx0 + 2];
                pin[0][rr][0] = a.x; pin[0][rr][1] = a.y; pin[0][rr][2] = b.x; pin[0][rr][3] = b.y;
                float2 c2 = *(float2*)&sm[vc + (cy + rr) * 34 + cx0];
                float2 d2 = *(float2*)&sm[vc + (cy + rr) * 34 + cx0 + 2];
                pin[1][rr][0] = c2.x; pin[1][rr][1] = c2.y; pin[1][rr][2] = d2.x; pin[1][rr][3] = d2.y;
            }
            float m0 = NEGINF, m1 = NEGINF;
            const float4* w4 = (const float4*)&sm[SM_WQC4];
#pragma unroll 2
            for (int c = 0; c < 10; c++) {
                float a0 = 0.f, a1 = 0.f;
#pragma unroll
                for (int cin = 0; cin < 2; cin++)
#pragma unroll
                    for (int ky = 0; ky < 3; ky++) {
                        float4 w = w4[(k * 10 + c) * 6 + cin * 3 + ky];
                        const float* q = pin[cin][ky];
                        a0 = fmaf(w.x, q[0], a0); a0 = fmaf(w.y, q[1], a0); a0 = fmaf(w.z, q[2], a0);
                        a1 = fmaf(w.x, q[1], a1); a1 = fmaf(w.y, q[2], a1); a1 = fmaf(w.z, q[3], a1);
                    }
                m0 = fmaxf(m0, a0); m1 = fmaxf(m1, a1);
            }
            sm[vn + (cy + 1) * 34 + cx0 + 1] = m0;
            sm[vn + (cy + 1) * 34 + cx0 + 2] = m1;
            scs0 += m0; scs1 += m1;
            __syncthreads();
            int tp = vc; vc = vn; vn = tp;
        }
        sm[SM_SC + cy * 32 + cx0] = scs0;
        sm[SM_SC + cy * 32 + cx0 + 1] = scs1;
    }
    __syncthreads();

    // ---- upsample (sum/4; jax half-pixel linear == clamp) -> m pairs ------
    for (int i = t; i < 4096; i += 512) {
        int oy = i >> 6, ox = i & 63, ty = oy >> 1, tx = ox >> 1;
        int ya, yb, xa, xb; float wya, wyb, wxa, wxb;
        if ((oy & 1) == 0) { ya = ty > 0 ? ty - 1 : 0; yb = ty; wya = 0.25f; wyb = 0.75f; }
        else { ya = ty; yb = ty < 31 ? ty + 1 : 31; wya = 0.75f; wyb = 0.25f; }
        if ((ox & 1) == 0) { xa = tx > 0 ? tx - 1 : 0; xb = tx; wxa = 0.25f; wxb = 0.75f; }
        else { xa = tx; xb = tx < 31 ? tx + 1 : 31; wxa = 0.75f; wxb = 0.25f; }
        float v = wya * (wxa * sm[SM_SC + ya * 32 + xa] + wxb * sm[SM_SC + ya * 32 + xb]) +
                  wyb * (wxa * sm[SM_SC + yb * 32 + xa] + wxb * sm[SM_SC + yb * 32 + xb]);
        wpair(sm, SM_ME, SM_MO, oy + 1, ox + 1, v * 0.25f);
    }
    // ---- fine r front -> r pairs -----------------------------------------
    for (int i = t; i < 4096; i += 512) {
        int y = i >> 6, x = i & 63;
        wpair(sm, SM_RE, SM_RO, y + 1, x + 1,
              rfront<64, 68, 4624>(&sm[SM_X], &sm[SM_W5F], &sm[SM_WCF], y, x));
    }
    __syncthreads();
    // ---- phase B: zero v pair buffers (kills X/X1/R1/CV*) -----------------
    for (int i = SM_X + t; i < SM_TOT; i += 512) sm[i] = 0.f;
    __syncthreads();

    // ==== fine VI: 1 col x 4 row-pairs/thread, conflict-free, CC=5 =========
    const int xc = t & 63, xp = xc + 1;     // column (padded)
    const int Y = (t >> 6) * 4;             // base row-pair, {0,4,...,28}
    int vE = SM_VAE, vO = SM_VAO, nE = SM_VBE, nO = SM_VBO;
    float S[8];
#pragma unroll
    for (int j = 0; j < 8; j++) S[j] = 0.f;
#pragma unroll 1
    for (int k = 0; k < KVI; k++) {
        float M[8];
#pragma unroll
        for (int j = 0; j < 8; j++) M[j] = NEGINF;
        const int e0b = SM_ME / 2 + Y * 68 + xp - 1;
        const int e1b = SM_RE / 2 + Y * 68 + xp - 1;
        const int e2b = vE / 2 + Y * 68 + xp - 1;
        const int o0b = SM_MO / 2 + Y * 68 + xp - 1;
        const int o1b = SM_RO / 2 + Y * 68 + xp - 1;
        const int o2b = vO / 2 + Y * 68 + xp - 1;
#pragma unroll 1
        for (int ch0 = 0; ch0 < 10; ch0 += 5) {
            ull A[5][4];
#pragma unroll
            for (int cc = 0; cc < 5; cc++)
#pragma unroll
                for (int j = 0; j < 4; j++) A[cc][j] = 0ull;
#pragma unroll
            for (int f = 0; f < 3; f++) {
                const int eb = (f == 0) ? e0b : (f == 1) ? e1b : e2b;
                const int ob = (f == 0) ? o0b : (f == 1) ? o1b : o2b;
#pragma unroll
                for (int kx = 0; kx < 3; kx++) {
                    const ull* qe = smu + eb + kx;
                    const ull* qo = smu + ob + kx;
                    ull e0 = qe[0], e1 = qe[68], e2 = qe[136], e3 = qe[204], e4 = qe[272];
                    ull o0 = qo[0], o1 = qo[68], o2 = qo[136], o3 = qo[204];
#pragma unroll
                    for (int cc = 0; cc < 5; cc++) {
                        const ull* w = smu + (k * 10 + ch0 + cc) * 27 + f * 9 + kx;
                        ull w0 = w[0], w1 = w[3], w2 = w[6];
                        fma2(A[cc][0], w0, e0); fma2(A[cc][0], w1, o0); fma2(A[cc][0], w2, e1);
                        fma2(A[cc][1], w0, e1); fma2(A[cc][1], w1, o1); fma2(A[cc][1], w2, e2);
                        fma2(A[cc][2], w0, e2); fma2(A[cc][2], w1, o2); fma2(A[cc][2], w2, e3);
                        fma2(A[cc][3], w0, e3); fma2(A[cc][3], w1, o3); fma2(A[cc][3], w2, e4);
                    }
                    asm volatile("" ::: "memory");  // bound load hoisting
                }
            }
#pragma unroll
            for (int cc = 0; cc < 5; cc++)
#pragma unroll
                for (int j = 0; j < 4; j++) {
                    float lo, hi;
                    upk2(A[cc][j], lo, hi);
                    M[2 * j] = fmaxf(M[2 * j], lo);
                    M[2 * j + 1] = fmaxf(M[2 * j + 1], hi);
                }
        }
#pragma unroll
        for (int j = 0; j < 4; j++) {
            float vlo = M[2 * j], vhi = M[2 * j + 1];
            smu[nO / 2 + (Y + j) * 68 + xp] = pk2(vlo, vhi);
            sm[nE + (Y + j) * 136 + 2 * xp + 1] = vlo;
            sm[nE + (Y + j + 1) * 136 + 2 * xp] = vhi;
            S[2 * j] += vlo; S[2 * j + 1] += vhi;
        }
        __syncthreads();
        int tp = vE; vE = nE; nE = tp; tp = vO; vO = nO; nO = tp;
    }

    // ---- vbar into current v buffer --------------------------------------
#pragma unroll
    for (int j = 0; j < 4; j++) {
        wpair(sm, vE, vO, 2 * (Y + j) + 1, xp, S[2 * j] * (1.f / 16.f));
        wpair(sm, vE, vO, 2 * (Y + j) + 2, xp, S[2 * j + 1] * (1.f / 16.f));
    }
    __syncthreads();

    // ---- final q conv + BN partials + gather -----------------------------
    const int Y5 = t >> 4, x05 = (t & 15) * 4;
    float pin[3][4][6];
#pragma unroll
    for (int rr = 0; rr < 4; rr++) {
        int p = 2 * Y5 + rr;
#pragma unroll
        for (int cc = 0; cc < 6; cc++) {
            int x = x05 + cc, off = (p >> 1) * 136 + 2 * x + (p & 1);
            pin[0][rr][cc] = sm[SM_ME + off];
            pin[1][rr][cc] = sm[SM_RE + off];
            pin[2][rr][cc] = sm[vE + off];
        }
    }
    const int s1 = S1[n], s2 = S2[n];
    float psum[10], psq[10];
#pragma unroll 2
    for (int c = 0; c < 10; c++) {
        const int wb = 2 * ((15 * 10 + c) * 27);
        float a[2][4];
#pragma unroll
        for (int j = 0; j < 8; j++) a[j >> 2][j & 3] = 0.f;
#pragma unroll
        for (int cin = 0; cin < 3; cin++)
#pragma unroll
            for (int ky = 0; ky < 3; ky++)
#pragma unroll
                for (int kx = 0; kx < 3; kx++) {
                    float wv = sm[wb + 2 * (cin * 9 + ky * 3 + kx)];
#pragma unroll
                    for (int dr = 0; dr < 2; dr++)
#pragma unroll
                        for (int dc = 0; dc < 4; dc++)
                            a[dr][dc] = fmaf(wv, pin[cin][dr + ky][dc + kx], a[dr][dc]);
                }
        float s = 0.f, q = 0.f;
#pragma unroll
        for (int dr = 0; dr < 2; dr++)
#pragma unroll
            for (int dc = 0; dc < 4; dc++) {
                s += a[dr][dc]; q += a[dr][dc] * a[dr][dc];
                if (2 * Y5 + dr == s1 && x05 + dc == s2) g_qout[n * 10 + c] = a[dr][dc];
            }
        psum[c] = s; psq[c] = q;
    }

    // ---- block-reduce BN partials ----------------------------------------
    int lane = t & 31, wid = t >> 5;
#pragma unroll
    for (int c = 0; c < 10; c++) {
        float s = psum[c], q = psq[c];
#pragma unroll
        for (int o = 16; o > 0; o >>= 1) {
            s += __shfl_down_sync(0xffffffffu, s, o);
            q += __shfl_down_sync(0xffffffffu, q, o);
        }
        if (lane == 0) { sm[SM_RED + wid * 20 + c] = s; sm[SM_RED + wid * 20 + 10 + c] = q; }
    }
    __syncthreads();
    if (t < 20) {
        float s = 0.f;
        for (int w = 0; w < 16; w++) s += sm[SM_RED + w * 20 + t];
        g_partial[n * 20 + t] = s;
    }

    // ---- epilogue by last block ------------------------------------------
    __shared__ int s_last;
    if (t == 0) {
        __threadfence();
        s_last = (atomicAdd(&g_tick, 1u) == N_IMG - 1);
    }
    __syncthreads();
    if (!s_last) return;
    if (t == 0) g_tick = 0;
    __threadfence();

    __shared__ float sMean[10], sScale[10], sBeta[10];
    if (t < 10) {
        double s = 0.0, sq = 0.0;
        for (int nn = 0; nn < N_IMG; nn++) {
            s += (double)g_partial[nn * 20 + t];
            sq += (double)g_partial[nn * 20 + 10 + t];
        }
        double cnt = (double)N_IMG * 4096.0, mu = s / cnt, var = sq / cnt - mu * mu;
        sMean[t] = (float)mu;
        sScale[t] = (float)((double)gamma[t] / sqrt(var + 1e-5));
        sBeta[t] = beta[t];
    }
    __syncthreads();
    if (t < N_IMG) {
        float qn[10];
#pragma unroll
        for (int c = 0; c < 10; c++)
            qn[c] = (g_qout[t * 10 + c] - sMean[c]) * sScale[c] + sBeta[c];
        float av = 0.f;
#pragma unroll
        for (int c = 0; c < 10; c++) av += qn[c] * dw1[c];
        av = fmaxf(av, 0.f);
        float b[8], bm = 0.f;
#pragma unroll
        for (int j = 0; j < 8; j++) {
            float bb = 0.f;
#pragma unroll
            for (int c = 0; c < 10; c++) bb += qn[c] * dw2[j * 10 + c];
            bb = fmaxf(bb, 0.f);
            b[j] = bb; bm += bb;
        }
        bm *= 0.125f;
#pragma unroll
        for (int j = 0; j < 8; j++) out[t * 8 + j] = av + b[j] - bm;
    }
}

extern "C" void kernel_launch(void* const* d_in, const int* in_sizes, int n_in,
                              void* d_out, int out_size) {
    const float* X   = (const float*)d_in[0];
    const int*   S1  = (const int*)d_in[1];
    const int*   S2  = (const int*)d_in[2];
    const float* whf = (const float*)d_in[3];
    const float* wrf = (const float*)d_in[4];
    const float* wqf = (const float*)d_in[5];
    const float* gam = (const float*)d_in[6];
    const float* bet = (const float*)d_in[7];
    const float* w1  = (const float*)d_in[8];
    const float* w2  = (const float*)d_in[9];
    const float* whc = (const float*)d_in[10];
    const float* wrc = (const float*)d_in[11];
    const float* wqc = (const float*)d_in[12];

    cudaFuncSetAttribute(k_main, cudaFuncAttributeMaxDynamicSharedMemorySize, SMEM_BYTES);
    k_main<<<N_IMG, 512, SMEM_BYTES>>>(X, S1, S2, wqf, wqc, whf, wrf, whc, wrc,
                                       gam, bet, w1, w2, (float*)d_out);
}